// round 8
// baseline (speedup 1.0000x reference)
#include <cuda_runtime.h>
#include <cuda_fp16.h>
#include <math.h>

#define NN 50000
#define EE 800000
#define FIN 128
#define HEADS 8
#define HID 32
#define FHID 256          // HEADS*HID
#define CC 40
#define NEG 0.2f

// ---------------- scratch (static device memory; no allocs allowed) --------
__device__ __half g_h1h[NN * FHID];       // x@W1 (fp16 messages)
__device__ float  g_out1[NN * FHID];      // elu(agg1 + b1)
__device__ float  g_as1[NN * HEADS];
__device__ float  g_ad1[NN * HEADS];
__device__ float  g_h2[NN * CC];          // out1@W2
__device__ float  g_as2[NN];
__device__ float  g_ad2[NN];
__device__ int    g_cnt[NN];              // degree, then scatter cursor
__device__ int    g_rowptr[NN + 1];
__device__ int    g_srci[EE + NN];        // src node per CSR slot (self-loops included)

// ---------------- helpers --------------------------------------------------
__device__ __forceinline__ float wredsum(float v) {
#pragma unroll
    for (int o = 16; o; o >>= 1) v += __shfl_xor_sync(0xffffffffu, v, o);
    return v;
}
// exp(leaky_relu(x)) — logits bounded ~|5|, no max-shift needed (shift-invariant softmax)
__device__ __forceinline__ float expw(float x) {
    return __expf(x > 0.f ? x : NEG * x);
}

// ---------------- CSR build ------------------------------------------------
__global__ void k_init_deg() {
    int v = blockIdx.x * blockDim.x + threadIdx.x;
    if (v < NN) g_cnt[v] = 1;  // self-loop
}

__global__ void k_hist(const int* __restrict__ ei) {
    int e = blockIdx.x * blockDim.x + threadIdx.x;
    if (e < EE) atomicAdd(&g_cnt[ei[EE + e]], 1);
}

// single-block shuffle scan
__global__ void k_scan() {
    __shared__ int wsum[32];
    __shared__ int carry_s;
    int tid = threadIdx.x, lane = tid & 31, wid = tid >> 5;
    if (tid == 0) { carry_s = 0; g_rowptr[0] = 0; }
    __syncthreads();
    for (int base = 0; base < NN; base += 1024) {
        int i = base + tid;
        int v = (i < NN) ? g_cnt[i] : 0;
#pragma unroll
        for (int o = 1; o < 32; o <<= 1) {
            int t = __shfl_up_sync(0xffffffffu, v, o);
            if (lane >= o) v += t;
        }
        if (lane == 31) wsum[wid] = v;
        __syncthreads();
        if (wid == 0) {
            int s = wsum[lane];
#pragma unroll
            for (int o = 1; o < 32; o <<= 1) {
                int t = __shfl_up_sync(0xffffffffu, s, o);
                if (lane >= o) s += t;
            }
            wsum[lane] = s;
        }
        __syncthreads();
        int pre = (wid ? wsum[wid - 1] : 0) + carry_s;
        if (i < NN) g_rowptr[i + 1] = pre + v;
        __syncthreads();
        if (tid == 0) carry_s += wsum[31];
        __syncthreads();
    }
}

__global__ void k_selfloop() {
    int v = blockIdx.x * blockDim.x + threadIdx.x;
    if (v < NN) {
        int p = g_rowptr[v];
        g_srci[p] = v;
        g_cnt[v] = p + 1;   // cursor past self-loop
    }
}

__global__ void k_scatter(const int* __restrict__ ei) {
    int e = blockIdx.x * blockDim.x + threadIdx.x;
    if (e < EE) {
        int dst = ei[EE + e];
        int src = ei[e];
        int pos = atomicAdd(&g_cnt[dst], 1);
        g_srci[pos] = src;
    }
}

// ---------------- GEMM1: h1 = x @ W1  (50000x128 @ 128x256), fp16 out ------
__global__ void k_gemm1(const float* __restrict__ x, const float* __restrict__ W) {
    __shared__ float As[64 * 16];
    __shared__ float Bs[16 * 64];
    int tid = threadIdx.x;
    int brow = blockIdx.y * 64, bcol = blockIdx.x * 64;
    int ty = tid / 16, tx = tid % 16;
    int ar = tid >> 2, ac = (tid & 3) * 4;
    int br = tid >> 4, bc = (tid & 15) * 4;
    float acc[4][4];
#pragma unroll
    for (int i = 0; i < 4; i++)
#pragma unroll
        for (int j = 0; j < 4; j++) acc[i][j] = 0.f;

    for (int kt = 0; kt < FIN; kt += 16) {
        float4 av = make_float4(0.f, 0.f, 0.f, 0.f);
        int grow = brow + ar;
        if (grow < NN) av = *(const float4*)(x + grow * FIN + kt + ac);
        *(float4*)(As + ar * 16 + ac) = av;
        *(float4*)(Bs + br * 64 + bc) = *(const float4*)(W + (kt + br) * FHID + bcol + bc);
        __syncthreads();
#pragma unroll
        for (int k = 0; k < 16; k++) {
            float a0 = As[(ty * 4 + 0) * 16 + k];
            float a1 = As[(ty * 4 + 1) * 16 + k];
            float a2 = As[(ty * 4 + 2) * 16 + k];
            float a3 = As[(ty * 4 + 3) * 16 + k];
            float4 b = *(float4*)(Bs + k * 64 + tx * 4);
            acc[0][0] += a0 * b.x; acc[0][1] += a0 * b.y; acc[0][2] += a0 * b.z; acc[0][3] += a0 * b.w;
            acc[1][0] += a1 * b.x; acc[1][1] += a1 * b.y; acc[1][2] += a1 * b.z; acc[1][3] += a1 * b.w;
            acc[2][0] += a2 * b.x; acc[2][1] += a2 * b.y; acc[2][2] += a2 * b.z; acc[2][3] += a2 * b.w;
            acc[3][0] += a3 * b.x; acc[3][1] += a3 * b.y; acc[3][2] += a3 * b.z; acc[3][3] += a3 * b.w;
        }
        __syncthreads();
    }
#pragma unroll
    for (int i = 0; i < 4; i++) {
        int row = brow + ty * 4 + i;
        if (row < NN) {
            __half2 h0 = __floats2half2_rn(acc[i][0], acc[i][1]);
            __half2 h1 = __floats2half2_rn(acc[i][2], acc[i][3]);
            uint2 u;
            u.x = *(unsigned*)&h0; u.y = *(unsigned*)&h1;
            *(uint2*)(g_h1h + row * FHID + bcol + tx * 4) = u;
        }
    }
}

// ---------------- attention logits, layer 1 (reads fp16 h1) ----------------
__global__ void k_alpha1(const float* __restrict__ a1s, const float* __restrict__ a1d) {
    int n = blockIdx.x;
    int tid = threadIdx.x;          // tid = head*32 + d  (matches [8,32] layout)
    int head = tid >> 5, d = tid & 31;
    float v = __half2float(g_h1h[n * FHID + tid]);
    float ps = wredsum(v * a1s[tid]);
    float pd = wredsum(v * a1d[tid]);
    if (d == 0) {
        g_as1[n * HEADS + head] = ps;
        g_ad1[n * HEADS + head] = pd;
    }
}

// ---------------- layer-1 single-pass softmax-agg + ELU --------------------
// 128 threads per node; thread owns features 2*tid, 2*tid+1 (head = tid>>4)
__global__ __launch_bounds__(128) void k_agg1(const float* __restrict__ b1) {
    int v = blockIdx.x;
    int tid = threadIdx.x;
    int head = tid >> 4;
    int beg = g_rowptr[v], deg = g_rowptr[v + 1] - beg;

    __shared__ int   s_src[32];
    __shared__ float s_w[32 * HEADS];
    __shared__ float s_ad[HEADS];
    if (tid < HEADS) s_ad[tid] = g_ad1[v * HEADS + tid];

    const __half2* hp = (const __half2*)g_h1h;
    float ax = 0.f, ay = 0.f, wsum = 0.f;

    for (int base = 0; base < deg; base += 32) {
        int cnt = min(32, deg - base);
        __syncthreads();                       // covers s_ad (1st iter) + smem reuse
        for (int it = tid; it < cnt * HEADS; it += 128) {
            int e = it >> 3, h = it & 7;
            int s = g_srci[beg + base + e];
            if (h == 0) s_src[e] = s;
            s_w[it] = expw(g_as1[s * HEADS + h] + s_ad[h]);
        }
        __syncthreads();
#pragma unroll 4
        for (int e = 0; e < cnt; e++) {
            float w = s_w[e * HEADS + head];
            float2 m = __half22float2(hp[s_src[e] * (FHID / 2) + tid]);
            ax += w * m.x;
            ay += w * m.y;
            wsum += w;
        }
    }
    float inv = 1.f / (wsum + 1e-16f);
    float r0 = ax * inv + b1[tid * 2];
    float r1 = ay * inv + b1[tid * 2 + 1];
    g_out1[v * FHID + tid * 2]     = r0 > 0.f ? r0 : expm1f(r0);
    g_out1[v * FHID + tid * 2 + 1] = r1 > 0.f ? r1 : expm1f(r1);
}

// ---------------- GEMM2: h2 = out1 @ W2  (50000x256 @ 256x40) --------------
__global__ void k_gemm2(const float* __restrict__ W2) {
    __shared__ float Ws[FHID * CC];   // 40 KB
    __shared__ float Xs[64 * 17];
    int tid = threadIdx.x;
    int brow = blockIdx.x * 64;
    for (int i = tid; i < FHID * CC; i += 256) Ws[i] = W2[i];
    int r = tid & 63, cg = tid >> 6;            // 4 col-groups of 10
    int lr = tid >> 2, lc = (tid & 3) * 4;
    float acc[10];
#pragma unroll
    for (int j = 0; j < 10; j++) acc[j] = 0.f;

    for (int kt = 0; kt < FHID; kt += 16) {
        __syncthreads();   // also protects Ws on first iter
        float4 xv = make_float4(0.f, 0.f, 0.f, 0.f);
        int grow = brow + lr;
        if (grow < NN) xv = *(const float4*)(g_out1 + grow * FHID + kt + lc);
        Xs[lr * 17 + lc + 0] = xv.x;
        Xs[lr * 17 + lc + 1] = xv.y;
        Xs[lr * 17 + lc + 2] = xv.z;
        Xs[lr * 17 + lc + 3] = xv.w;
        __syncthreads();
#pragma unroll
        for (int k = 0; k < 16; k++) {
            float x = Xs[r * 17 + k];
            const float* wp = Ws + (kt + k) * CC + cg * 10;
#pragma unroll
            for (int j = 0; j < 10; j++) acc[j] += x * wp[j];
        }
    }
    int row = brow + r;
    if (row < NN) {
#pragma unroll
        for (int j = 0; j < 10; j++) g_h2[row * CC + cg * 10 + j] = acc[j];
    }
}

// ---------------- attention logits, layer 2 --------------------------------
__global__ void k_alpha2(const float* __restrict__ a2s, const float* __restrict__ a2d) {
    int n = blockIdx.x * blockDim.x + threadIdx.x;
    if (n >= NN) return;
    float s = 0.f, d = 0.f;
#pragma unroll
    for (int k = 0; k < CC; k++) {
        float v = g_h2[n * CC + k];
        s += v * a2s[k];
        d += v * a2d[k];
    }
    g_as2[n] = s;
    g_ad2[n] = d;
}

// ---------------- layer-2 single-pass softmax-agg: warp per node -----------
__global__ __launch_bounds__(256) void k_agg2w(const float* __restrict__ b2,
                                               float* __restrict__ out) {
    int w = (blockIdx.x * blockDim.x + threadIdx.x) >> 5;
    if (w >= NN) return;
    int lane = threadIdx.x & 31;
    int beg = g_rowptr[w], deg = g_rowptr[w + 1] - beg;
    float adv = g_ad2[w];

    float a0 = 0.f, a1 = 0.f, wsum = 0.f;
#pragma unroll 4
    for (int i = 0; i < deg; i++) {
        int s = g_srci[beg + i];
        float wt = expw(g_as2[s] + adv);
        a0 += wt * g_h2[s * CC + lane];
        if (lane < CC - 32) a1 += wt * g_h2[s * CC + 32 + lane];
        wsum += wt;
    }
    float inv = 1.f / (wsum + 1e-16f);
    out[w * CC + lane] = a0 * inv + b2[lane];
    if (lane < CC - 32) out[w * CC + 32 + lane] = a1 * inv + b2[32 + lane];
}

// ---------------- launch ---------------------------------------------------
extern "C" void kernel_launch(void* const* d_in, const int* in_sizes, int n_in,
                              void* d_out, int out_size) {
    const float* x   = (const float*)d_in[0];
    const int*   ei  = (const int*)d_in[1];      // int32 edge_index [2, E]
    const float* W1  = (const float*)d_in[2];
    const float* a1s = (const float*)d_in[3];
    const float* a1d = (const float*)d_in[4];
    const float* b1  = (const float*)d_in[5];
    const float* W2  = (const float*)d_in[6];
    const float* a2s = (const float*)d_in[7];
    const float* a2d = (const float*)d_in[8];
    const float* b2  = (const float*)d_in[9];
    float*       out = (float*)d_out;

    // CSR build (dst-grouped, self-loops first)
    k_init_deg<<<(NN + 255) / 256, 256>>>();
    k_hist<<<(EE + 255) / 256, 256>>>(ei);
    k_scan<<<1, 1024>>>();
    k_selfloop<<<(NN + 255) / 256, 256>>>();
    k_scatter<<<(EE + 255) / 256, 256>>>(ei);

    // layer 1
    dim3 g1(FHID / 64, (NN + 63) / 64);
    k_gemm1<<<g1, 256>>>(x, W1);
    k_alpha1<<<NN, 256>>>(a1s, a1d);
    k_agg1<<<NN, 128>>>(b1);

    // layer 2
    k_gemm2<<<(NN + 63) / 64, 256>>>(W2);
    k_alpha2<<<(NN + 255) / 256, 256>>>(a2s, a2d);
    k_agg2w<<<(NN * 32 + 255) / 256, 256>>>(b2, out);
}

// round 10
// speedup vs baseline: 1.5319x; 1.5319x over previous
#include <cuda_runtime.h>
#include <cuda_fp16.h>
#include <math.h>

#define NN 50000
#define EE 800000
#define FIN 128
#define HEADS 8
#define HID 32
#define FHID 256          // HEADS*HID
#define CC 40
#define NEG 0.2f
#define AST 136           // padded smem stride (halfs): 272B = 17*16 (uint4-aligned), conflict-free

// ---------------- scratch (static device memory; no allocs allowed) --------
__device__ float  g_h1[NN * FHID];        // x@W1 (fp32)
__device__ __half g_xh[NN * FIN];         // x in fp16
__device__ __half g_w1t[FHID * FIN];      // W1 transposed [n][k] fp16
__device__ float  g_out1[NN * FHID];      // elu(agg1 + b1)
__device__ float  g_as1[NN * HEADS];
__device__ float  g_ad1[NN * HEADS];
__device__ float  g_h2[NN * CC];          // out1@W2
__device__ float  g_as2[NN];
__device__ float  g_ad2[NN];
__device__ int    g_cnt[NN];              // degree, then scatter cursor
__device__ int    g_rowptr[NN + 1];
__device__ int    g_srci[EE + NN];        // src node per CSR slot (self-loops included)

// ---------------- helpers --------------------------------------------------
__device__ __forceinline__ float wredmax(float v) {
#pragma unroll
    for (int o = 16; o; o >>= 1) v = fmaxf(v, __shfl_xor_sync(0xffffffffu, v, o));
    return v;
}
__device__ __forceinline__ float wredsum(float v) {
#pragma unroll
    for (int o = 16; o; o >>= 1) v += __shfl_xor_sync(0xffffffffu, v, o);
    return v;
}
__device__ __forceinline__ float lrelu(float x) { return x > 0.f ? x : NEG * x; }

// ---------------- CSR build ------------------------------------------------
__global__ void k_init_deg() {
    int v = blockIdx.x * blockDim.x + threadIdx.x;
    if (v < NN) g_cnt[v] = 1;  // self-loop
}

__global__ void k_hist(const int* __restrict__ ei) {
    int e = blockIdx.x * blockDim.x + threadIdx.x;
    if (e < EE) atomicAdd(&g_cnt[ei[EE + e]], 1);
}

// single-block shuffle scan
__global__ void k_scan() {
    __shared__ int wsum[32];
    __shared__ int carry_s;
    int tid = threadIdx.x, lane = tid & 31, wid = tid >> 5;
    if (tid == 0) { carry_s = 0; g_rowptr[0] = 0; }
    __syncthreads();
    for (int base = 0; base < NN; base += 1024) {
        int i = base + tid;
        int v = (i < NN) ? g_cnt[i] : 0;
#pragma unroll
        for (int o = 1; o < 32; o <<= 1) {
            int t = __shfl_up_sync(0xffffffffu, v, o);
            if (lane >= o) v += t;
        }
        if (lane == 31) wsum[wid] = v;
        __syncthreads();
        if (wid == 0) {
            int s = wsum[lane];
#pragma unroll
            for (int o = 1; o < 32; o <<= 1) {
                int t = __shfl_up_sync(0xffffffffu, s, o);
                if (lane >= o) s += t;
            }
            wsum[lane] = s;
        }
        __syncthreads();
        int pre = (wid ? wsum[wid - 1] : 0) + carry_s;
        if (i < NN) g_rowptr[i + 1] = pre + v;
        __syncthreads();
        if (tid == 0) carry_s += wsum[31];
        __syncthreads();
    }
}

__global__ void k_selfloop() {
    int v = blockIdx.x * blockDim.x + threadIdx.x;
    if (v < NN) {
        int p = g_rowptr[v];
        g_srci[p] = v;
        g_cnt[v] = p + 1;   // cursor past self-loop
    }
}

__global__ void k_scatter(const int* __restrict__ ei) {
    int e = blockIdx.x * blockDim.x + threadIdx.x;
    if (e < EE) {
        int dst = ei[EE + e];
        int src = ei[e];
        int pos = atomicAdd(&g_cnt[dst], 1);
        g_srci[pos] = src;
    }
}

// ---------------- fp16 conversions -----------------------------------------
__global__ void k_cvtx(const float* __restrict__ x) {
    int i = blockIdx.x * blockDim.x + threadIdx.x;   // over float4 groups
    if (i < NN * FIN / 4) {
        float4 v = *(const float4*)(x + i * 4);
        __half2 h0 = __floats2half2_rn(v.x, v.y);
        __half2 h1 = __floats2half2_rn(v.z, v.w);
        uint2 u; u.x = *(unsigned*)&h0; u.y = *(unsigned*)&h1;
        *(uint2*)(g_xh + i * 4) = u;
    }
}

__global__ void k_cvtw(const float* __restrict__ W1) {
    int i = blockIdx.x * blockDim.x + threadIdx.x;   // i = n*FIN + k
    if (i < FHID * FIN) {
        int n = i >> 7, k = i & 127;
        g_w1t[i] = __float2half(W1[k * FHID + n]);
    }
}

// ---------------- GEMM1 (tensor core): h1 = x @ W1 -------------------------
// block tile M128 x N32, K=128 fully resident; 8 warps (4m x 2n), warp m32 x n16
__global__ __launch_bounds__(256) void k_gemm1_tc() {
    __shared__ __half As[128 * AST];
    __shared__ __half Bs[32 * AST];
    int tid = threadIdx.x;
    int warp = tid >> 5, lane = tid & 31;
    int brow = blockIdx.x * 128;
    int bcol = blockIdx.y * 32;

    // load A: 128 rows x 128 halfs (uint4 = 8 halfs each, 2048 total)
    for (int i = tid; i < 128 * 16; i += 256) {
        int r = i >> 4, c = (i & 15) * 8;
        uint4 v = make_uint4(0, 0, 0, 0);
        int gr = brow + r;
        if (gr < NN) v = *(const uint4*)(g_xh + gr * FIN + c);
        *(uint4*)(As + r * AST + c) = v;
    }
    // load B: 32 n-rows x 128 k halfs from pre-transposed W1
    for (int i = tid; i < 32 * 16; i += 256) {
        int n = i >> 4, c = (i & 15) * 8;
        *(uint4*)(Bs + n * AST + c) = *(const uint4*)(g_w1t + (bcol + n) * FIN + c);
    }
    __syncthreads();

    int wm = (warp & 3) * 32;    // warp m offset
    int wn = (warp >> 2) * 16;   // warp n offset
    int gid = lane >> 2, tig = lane & 3;

    float acc[2][2][4];
#pragma unroll
    for (int mi = 0; mi < 2; mi++)
#pragma unroll
        for (int ni = 0; ni < 2; ni++)
#pragma unroll
            for (int j = 0; j < 4; j++) acc[mi][ni][j] = 0.f;

#pragma unroll
    for (int k0 = 0; k0 < FIN; k0 += 16) {
        unsigned a[2][4], b[2][2];
#pragma unroll
        for (int mi = 0; mi < 2; mi++) {
            const __half* ap = As + (wm + mi * 16 + gid) * AST + k0 + tig * 2;
            a[mi][0] = *(const unsigned*)(ap);
            a[mi][1] = *(const unsigned*)(ap + 8 * AST);
            a[mi][2] = *(const unsigned*)(ap + 8);
            a[mi][3] = *(const unsigned*)(ap + 8 * AST + 8);
        }
#pragma unroll
        for (int ni = 0; ni < 2; ni++) {
            const __half* bp = Bs + (wn + ni * 8 + gid) * AST + k0 + tig * 2;
            b[ni][0] = *(const unsigned*)(bp);
            b[ni][1] = *(const unsigned*)(bp + 8);
        }
#pragma unroll
        for (int mi = 0; mi < 2; mi++)
#pragma unroll
            for (int ni = 0; ni < 2; ni++) {
                asm volatile(
                    "mma.sync.aligned.m16n8k16.row.col.f32.f16.f16.f32 "
                    "{%0,%1,%2,%3}, {%4,%5,%6,%7}, {%8,%9}, {%0,%1,%2,%3};\n"
                    : "+f"(acc[mi][ni][0]), "+f"(acc[mi][ni][1]),
                      "+f"(acc[mi][ni][2]), "+f"(acc[mi][ni][3])
                    : "r"(a[mi][0]), "r"(a[mi][1]), "r"(a[mi][2]), "r"(a[mi][3]),
                      "r"(b[ni][0]), "r"(b[ni][1]));
            }
    }

    // epilogue: fp32 store
#pragma unroll
    for (int mi = 0; mi < 2; mi++) {
        int r0 = brow + wm + mi * 16 + gid;
#pragma unroll
        for (int ni = 0; ni < 2; ni++) {
            int col = bcol + wn + ni * 8 + tig * 2;
            if (r0 < NN)
                *(float2*)(g_h1 + r0 * FHID + col) = make_float2(acc[mi][ni][0], acc[mi][ni][1]);
            if (r0 + 8 < NN)
                *(float2*)(g_h1 + (r0 + 8) * FHID + col) = make_float2(acc[mi][ni][2], acc[mi][ni][3]);
        }
    }
}

// ---------------- attention logits, layer 1 --------------------------------
__global__ void k_alpha1(const float* __restrict__ a1s, const float* __restrict__ a1d) {
    int n = blockIdx.x;
    int tid = threadIdx.x;          // tid = head*32 + d  (matches [8,32] layout)
    int head = tid >> 5, d = tid & 31;
    float v = g_h1[n * FHID + tid];
    float ps = wredsum(v * a1s[tid]);
    float pd = wredsum(v * a1d[tid]);
    if (d == 0) {
        g_as1[n * HEADS + head] = ps;
        g_ad1[n * HEADS + head] = pd;
    }
}

// ---------------- layer-1 segment softmax + aggregation + ELU (R4) ---------
__global__ void k_agg1(const float* __restrict__ b1) {
    int v = blockIdx.x;
    int beg = g_rowptr[v], end = g_rowptr[v + 1];
    int deg = end - beg;
    int tid = threadIdx.x, lane = tid & 31, head = tid >> 5;

    __shared__ float smx[HEADS], sinv[HEADS];
    __shared__ int   s_src[32];
    __shared__ float s_w[32 * HEADS];

    float adv = g_ad1[v * HEADS + head];
    // phase 1: per-head max
    float mx = -1e30f;
    for (int i = lane; i < deg; i += 32) {
        float e = lrelu(g_as1[g_srci[beg + i] * HEADS + head] + adv);
        mx = fmaxf(mx, e);
    }
    mx = wredmax(mx);
    // phase 2: per-head sum of exp
    float sm = 0.f;
    for (int i = lane; i < deg; i += 32) {
        float e = lrelu(g_as1[g_srci[beg + i] * HEADS + head] + adv);
        sm += expf(e - mx);
    }
    sm = wredsum(sm);
    if (lane == 0) { smx[head] = mx; sinv[head] = 1.f / (sm + 1e-16f); }
    __syncthreads();

    // phase 3: weighted aggregation, chunked
    float acc = 0.f;
    for (int base = 0; base < deg; base += 32) {
        int cnt = min(32, deg - base);
        int el = tid >> 3, hh = tid & 7;
        if (el < cnt) {
            int s = g_srci[beg + base + el];
            if (hh == 0) s_src[el] = s;
            float e = lrelu(g_as1[s * HEADS + hh] + g_ad1[v * HEADS + hh]);
            s_w[el * HEADS + hh] = expf(e - smx[hh]) * sinv[hh];
        }
        __syncthreads();
        for (int e = 0; e < cnt; e++) {
            float w = s_w[e * HEADS + head];
            acc += g_h1[s_src[e] * FHID + tid] * w;
        }
        __syncthreads();
    }
    float r = acc + b1[tid];
    g_out1[v * FHID + tid] = r > 0.f ? r : expm1f(r);   // ELU
}

// ---------------- GEMM2: h2 = out1 @ W2  (50000x256 @ 256x40) --------------
__global__ void k_gemm2(const float* __restrict__ W2) {
    __shared__ float Ws[FHID * CC];   // 40 KB
    __shared__ float Xs[64 * 17];
    int tid = threadIdx.x;
    int brow = blockIdx.x * 64;
    for (int i = tid; i < FHID * CC; i += 256) Ws[i] = W2[i];
    int r = tid & 63, cg = tid >> 6;            // 4 col-groups of 10
    int lr = tid >> 2, lc = (tid & 3) * 4;
    float acc[10];
#pragma unroll
    for (int j = 0; j < 10; j++) acc[j] = 0.f;

    for (int kt = 0; kt < FHID; kt += 16) {
        __syncthreads();   // also protects Ws on first iter
        float4 xv = make_float4(0.f, 0.f, 0.f, 0.f);
        int grow = brow + lr;
        if (grow < NN) xv = *(const float4*)(g_out1 + grow * FHID + kt + lc);
        Xs[lr * 17 + lc + 0] = xv.x;
        Xs[lr * 17 + lc + 1] = xv.y;
        Xs[lr * 17 + lc + 2] = xv.z;
        Xs[lr * 17 + lc + 3] = xv.w;
        __syncthreads();
#pragma unroll
        for (int k = 0; k < 16; k++) {
            float x = Xs[r * 17 + k];
            const float* wp = Ws + (kt + k) * CC + cg * 10;
#pragma unroll
            for (int j = 0; j < 10; j++) acc[j] += x * wp[j];
        }
    }
    int row = brow + r;
    if (row < NN) {
#pragma unroll
        for (int j = 0; j < 10; j++) g_h2[row * CC + cg * 10 + j] = acc[j];
    }
}

// ---------------- attention logits, layer 2 --------------------------------
__global__ void k_alpha2(const float* __restrict__ a2s, const float* __restrict__ a2d) {
    int n = blockIdx.x * blockDim.x + threadIdx.x;
    if (n >= NN) return;
    float s = 0.f, d = 0.f;
#pragma unroll
    for (int k = 0; k < CC; k++) {
        float v = g_h2[n * CC + k];
        s += v * a2s[k];
        d += v * a2d[k];
    }
    g_as2[n] = s;
    g_ad2[n] = d;
}

// ---------------- layer-2 segment softmax + aggregation (R4) ---------------
__global__ void k_agg2(const float* __restrict__ b2, float* __restrict__ out) {
    int v = blockIdx.x;
    int beg = g_rowptr[v], end = g_rowptr[v + 1];
    int deg = end - beg;
    int tid = threadIdx.x;

    __shared__ float smx, sinvs;
    __shared__ int   s_src[64];
    __shared__ float s_w[64];

    float adv = g_ad2[v];
    if (tid < 32) {
        float mx = -1e30f;
        for (int i = tid; i < deg; i += 32)
            mx = fmaxf(mx, lrelu(g_as2[g_srci[beg + i]] + adv));
        mx = wredmax(mx);
        float sm = 0.f;
        for (int i = tid; i < deg; i += 32)
            sm += expf(lrelu(g_as2[g_srci[beg + i]] + adv) - mx);
        sm = wredsum(sm);
        if (tid == 0) { smx = mx; sinvs = 1.f / (sm + 1e-16f); }
    }
    __syncthreads();
    float mx = smx, inv = sinvs;
    float acc = 0.f;
    for (int base = 0; base < deg; base += 64) {
        int cnt = min(64, deg - base);
        if (tid < cnt) {
            int s = g_srci[beg + base + tid];
            s_src[tid] = s;
            float e = lrelu(g_as2[s] + adv);
            s_w[tid] = expf(e - mx) * inv;
        }
        __syncthreads();
        if (tid < CC) {
            for (int e = 0; e < cnt; e++)
                acc += g_h2[s_src[e] * CC + tid] * s_w[e];
        }
        __syncthreads();
    }
    if (tid < CC) out[v * CC + tid] = acc + b2[tid];
}

// ---------------- launch ---------------------------------------------------
extern "C" void kernel_launch(void* const* d_in, const int* in_sizes, int n_in,
                              void* d_out, int out_size) {
    const float* x   = (const float*)d_in[0];
    const int*   ei  = (const int*)d_in[1];      // int32 edge_index [2, E]
    const float* W1  = (const float*)d_in[2];
    const float* a1s = (const float*)d_in[3];
    const float* a1d = (const float*)d_in[4];
    const float* b1  = (const float*)d_in[5];
    const float* W2  = (const float*)d_in[6];
    const float* a2s = (const float*)d_in[7];
    const float* a2d = (const float*)d_in[8];
    const float* b2  = (const float*)d_in[9];
    float*       out = (float*)d_out;

    // CSR build (dst-grouped, self-loops first)
    k_init_deg<<<(NN + 255) / 256, 256>>>();
    k_hist<<<(EE + 255) / 256, 256>>>(ei);
    k_scan<<<1, 1024>>>();
    k_selfloop<<<(NN + 255) / 256, 256>>>();
    k_scatter<<<(EE + 255) / 256, 256>>>(ei);

    // fp16 conversions for tensor-core GEMM1
    k_cvtx<<<(NN * FIN / 4 + 255) / 256, 256>>>(x);
    k_cvtw<<<(FHID * FIN + 255) / 256, 256>>>(W1);

    // layer 1
    dim3 g1((NN + 127) / 128, FHID / 32);
    k_gemm1_tc<<<g1, 256>>>();
    k_alpha1<<<NN, 256>>>(a1s, a1d);
    k_agg1<<<NN, 256>>>(b1);

    // layer 2
    k_gemm2<<<(NN + 63) / 64, 256>>>(W2);
    k_alpha2<<<(NN + 255) / 256, 256>>>(a2s, a2d);
    k_agg2<<<NN, 64>>>(b2, out);
}

// round 14
// speedup vs baseline: 1.8914x; 1.2347x over previous
#include <cuda_runtime.h>
#include <cuda_fp16.h>
#include <math.h>

#define NN 50000
#define EE 800000
#define FIN 128
#define HEADS 8
#define HID 32
#define FHID 256          // HEADS*HID
#define CC 40
#define NEG 0.2f
#define AST 136           // padded smem stride (halfs): 272B = 17*16 (uint4-aligned), conflict-free
#define SCB 49            // scan blocks (1024 elems each covers 50176 >= NN)

// ---------------- scratch (static device memory; no allocs allowed) --------
__device__ float  g_h1[NN * FHID];        // x@W1 (fp32)
__device__ __half g_xh[NN * FIN];         // x in fp16
__device__ __half g_w1t[FHID * FIN];      // W1 transposed [n][k] fp16
__device__ float  g_out1[NN * FHID];      // elu(agg1 + b1)
__device__ float  g_as1[NN * HEADS];
__device__ float  g_ad1[NN * HEADS];
__device__ float  g_h2[NN * CC];          // out1@W2
__device__ float  g_as2[NN];
__device__ float  g_ad2[NN];
__device__ int    g_cnt[NN];              // degree, then scatter cursor
__device__ int    g_rowptr[NN + 1];
__device__ int    g_bsum[SCB];            // scan partials
__device__ int    g_boff[SCB];            // scan offsets
__device__ int    g_srci[EE + NN];        // src node per CSR slot (self-loops included)

// ---------------- helpers --------------------------------------------------
__device__ __forceinline__ float lrelu(float x) { return x > 0.f ? x : NEG * x; }

// ---------------- CSR build ------------------------------------------------
__global__ void k_init_deg() {
    int v = blockIdx.x * blockDim.x + threadIdx.x;
    if (v < NN) g_cnt[v] = 1;  // self-loop
}

__global__ void k_hist(const int* __restrict__ ei) {
    int e = blockIdx.x * blockDim.x + threadIdx.x;
    if (e < EE) atomicAdd(&g_cnt[ei[EE + e]], 1);
}

// multi-block scan, stage 1: each block inclusive-scans its 1024 elements
__global__ void k_scan1() {
    __shared__ int wsum[32];
    int tid = threadIdx.x, lane = tid & 31, wid = tid >> 5;
    int i = blockIdx.x * 1024 + tid;
    int v = (i < NN) ? g_cnt[i] : 0;
#pragma unroll
    for (int o = 1; o < 32; o <<= 1) {
        int t = __shfl_up_sync(0xffffffffu, v, o);
        if (lane >= o) v += t;
    }
    if (lane == 31) wsum[wid] = v;
    __syncthreads();
    if (wid == 0) {
        int s = wsum[lane];
#pragma unroll
        for (int o = 1; o < 32; o <<= 1) {
            int t = __shfl_up_sync(0xffffffffu, s, o);
            if (lane >= o) s += t;
        }
        wsum[lane] = s;
    }
    __syncthreads();
    int incl = v + (wid ? wsum[wid - 1] : 0);
    if (i < NN) g_rowptr[i + 1] = incl;       // block-local inclusive
    if (tid == 1023) g_bsum[blockIdx.x] = incl;
}

// stage 2: exclusive scan of SCB block sums — simple and covers ALL entries
__global__ void k_scan2() {
    __shared__ int s[SCB];
    int lane = threadIdx.x;
    for (int b = lane; b < SCB; b += 32) s[b] = g_bsum[b];
    __syncwarp();
    if (lane == 0) {
        int acc = 0;
        for (int b = 0; b < SCB; b++) { int t = s[b]; s[b] = acc; acc += t; }
    }
    __syncwarp();
    for (int b = lane; b < SCB; b += 32) g_boff[b] = s[b];
}

// stage 3: add block offsets
__global__ void k_scan3() {
    int i = blockIdx.x * 1024 + threadIdx.x;
    int off = g_boff[blockIdx.x];
    if (i < NN) g_rowptr[i + 1] += off;
    if (i == 0) g_rowptr[0] = 0;
}

__global__ void k_selfloop() {
    int v = blockIdx.x * blockDim.x + threadIdx.x;
    if (v < NN) {
        int p = g_rowptr[v];
        g_srci[p] = v;
        g_cnt[v] = p + 1;   // cursor past self-loop
    }
}

__global__ void k_scatter(const int* __restrict__ ei) {
    int e = blockIdx.x * blockDim.x + threadIdx.x;
    if (e < EE) {
        int dst = ei[EE + e];
        int src = ei[e];
        int pos = atomicAdd(&g_cnt[dst], 1);
        g_srci[pos] = src;
    }
}

// ---------------- fp16 conversions -----------------------------------------
__global__ void k_cvtx(const float* __restrict__ x) {
    int i = blockIdx.x * blockDim.x + threadIdx.x;   // over float4 groups
    if (i < NN * FIN / 4) {
        float4 v = *(const float4*)(x + i * 4);
        __half2 h0 = __floats2half2_rn(v.x, v.y);
        __half2 h1 = __floats2half2_rn(v.z, v.w);
        uint2 u; u.x = *(unsigned*)&h0; u.y = *(unsigned*)&h1;
        *(uint2*)(g_xh + i * 4) = u;
    }
}

__global__ void k_cvtw(const float* __restrict__ W1) {
    int i = blockIdx.x * blockDim.x + threadIdx.x;   // i = n*FIN + k
    if (i < FHID * FIN) {
        int n = i >> 7, k = i & 127;
        g_w1t[i] = __float2half(W1[k * FHID + n]);
    }
}

// ---------------- GEMM1 (tensor core): h1 = x @ W1 -------------------------
// block tile M128 x N32, K=128 fully resident; 8 warps (4m x 2n), warp m32 x n16
__global__ __launch_bounds__(256) void k_gemm1_tc() {
    __shared__ __half As[128 * AST];
    __shared__ __half Bs[32 * AST];
    int tid = threadIdx.x;
    int warp = tid >> 5, lane = tid & 31;
    int brow = blockIdx.x * 128;
    int bcol = blockIdx.y * 32;

    for (int i = tid; i < 128 * 16; i += 256) {
        int r = i >> 4, c = (i & 15) * 8;
        uint4 v = make_uint4(0, 0, 0, 0);
        int gr = brow + r;
        if (gr < NN) v = *(const uint4*)(g_xh + gr * FIN + c);
        *(uint4*)(As + r * AST + c) = v;
    }
    for (int i = tid; i < 32 * 16; i += 256) {
        int n = i >> 4, c = (i & 15) * 8;
        *(uint4*)(Bs + n * AST + c) = *(const uint4*)(g_w1t + (bcol + n) * FIN + c);
    }
    __syncthreads();

    int wm = (warp & 3) * 32;    // warp m offset
    int wn = (warp >> 2) * 16;   // warp n offset
    int gid = lane >> 2, tig = lane & 3;

    float acc[2][2][4];
#pragma unroll
    for (int mi = 0; mi < 2; mi++)
#pragma unroll
        for (int ni = 0; ni < 2; ni++)
#pragma unroll
            for (int j = 0; j < 4; j++) acc[mi][ni][j] = 0.f;

#pragma unroll
    for (int k0 = 0; k0 < FIN; k0 += 16) {
        unsigned a[2][4], b[2][2];
#pragma unroll
        for (int mi = 0; mi < 2; mi++) {
            const __half* ap = As + (wm + mi * 16 + gid) * AST + k0 + tig * 2;
            a[mi][0] = *(const unsigned*)(ap);
            a[mi][1] = *(const unsigned*)(ap + 8 * AST);
            a[mi][2] = *(const unsigned*)(ap + 8);
            a[mi][3] = *(const unsigned*)(ap + 8 * AST + 8);
        }
#pragma unroll
        for (int ni = 0; ni < 2; ni++) {
            const __half* bp = Bs + (wn + ni * 8 + gid) * AST + k0 + tig * 2;
            b[ni][0] = *(const unsigned*)(bp);
            b[ni][1] = *(const unsigned*)(bp + 8);
        }
#pragma unroll
        for (int mi = 0; mi < 2; mi++)
#pragma unroll
            for (int ni = 0; ni < 2; ni++) {
                asm volatile(
                    "mma.sync.aligned.m16n8k16.row.col.f32.f16.f16.f32 "
                    "{%0,%1,%2,%3}, {%4,%5,%6,%7}, {%8,%9}, {%0,%1,%2,%3};\n"
                    : "+f"(acc[mi][ni][0]), "+f"(acc[mi][ni][1]),
                      "+f"(acc[mi][ni][2]), "+f"(acc[mi][ni][3])
                    : "r"(a[mi][0]), "r"(a[mi][1]), "r"(a[mi][2]), "r"(a[mi][3]),
                      "r"(b[ni][0]), "r"(b[ni][1]));
            }
    }

#pragma unroll
    for (int mi = 0; mi < 2; mi++) {
        int r0 = brow + wm + mi * 16 + gid;
#pragma unroll
        for (int ni = 0; ni < 2; ni++) {
            int col = bcol + wn + ni * 8 + tig * 2;
            if (r0 < NN)
                *(float2*)(g_h1 + r0 * FHID + col) = make_float2(acc[mi][ni][0], acc[mi][ni][1]);
            if (r0 + 8 < NN)
                *(float2*)(g_h1 + (r0 + 8) * FHID + col) = make_float2(acc[mi][ni][2], acc[mi][ni][3]);
        }
    }
}

// ---------------- attention logits, layer 1 --------------------------------
__global__ void k_alpha1(const float* __restrict__ a1s, const float* __restrict__ a1d) {
    int n = blockIdx.x;
    int tid = threadIdx.x;          // tid = head*32 + d  (matches [8,32] layout)
    int head = tid >> 5, d = tid & 31;
    float v = g_h1[n * FHID + tid];
    float ps = v * a1s[tid];
    float pd = v * a1d[tid];
#pragma unroll
    for (int o = 16; o; o >>= 1) {
        ps += __shfl_xor_sync(0xffffffffu, ps, o);
        pd += __shfl_xor_sync(0xffffffffu, pd, o);
    }
    if (d == 0) {
        g_as1[n * HEADS + head] = ps;
        g_ad1[n * HEADS + head] = pd;
    }
}

// ---------------- layer-1 single-pass softmax-agg + ELU --------------------
// R10 geometry (256 thr/node, fp32 gather); max/sum pre-passes removed
// (shift-invariant softmax, logits bounded): acc/wsum computed in one sweep.
__global__ void k_agg1(const float* __restrict__ b1) {
    int v = blockIdx.x;
    int beg = g_rowptr[v], end = g_rowptr[v + 1];
    int deg = end - beg;
    int tid = threadIdx.x, head = tid >> 5;

    __shared__ int   s_src[32];
    __shared__ float s_w[32 * HEADS];
    __shared__ float s_ad[HEADS];
    if (tid < HEADS) s_ad[tid] = g_ad1[v * HEADS + tid];

    float acc = 0.f, wsum = 0.f;
    for (int base = 0; base < deg; base += 32) {
        int cnt = min(32, deg - base);
        __syncthreads();                      // covers s_ad (1st iter) + smem reuse
        int el = tid >> 3, hh = tid & 7;
        if (el < cnt) {
            int s = g_srci[beg + base + el];
            if (hh == 0) s_src[el] = s;
            s_w[el * HEADS + hh] = __expf(lrelu(g_as1[s * HEADS + hh] + s_ad[hh]));
        }
        __syncthreads();
        for (int e = 0; e < cnt; e++) {
            float w = s_w[e * HEADS + head];
            acc += g_h1[s_src[e] * FHID + tid] * w;
            wsum += w;                        // identical across threads of a head
        }
    }
    float r = acc / (wsum + 1e-16f) + b1[tid];
    g_out1[v * FHID + tid] = r > 0.f ? r : expm1f(r);   // ELU
}

// ---------------- GEMM2: h2 = out1 @ W2  (50000x256 @ 256x40) --------------
__global__ void k_gemm2(const float* __restrict__ W2) {
    __shared__ float Ws[FHID * CC];   // 40 KB
    __shared__ float Xs[64 * 17];
    int tid = threadIdx.x;
    int brow = blockIdx.x * 64;
    for (int i = tid; i < FHID * CC; i += 256) Ws[i] = W2[i];
    int r = tid & 63, cg = tid >> 6;            // 4 col-groups of 10
    int lr = tid >> 2, lc = (tid & 3) * 4;
    float acc[10];
#pragma unroll
    for (int j = 0; j < 10; j++) acc[j] = 0.f;

    for (int kt = 0; kt < FHID; kt += 16) {
        __syncthreads();   // also protects Ws on first iter
        float4 xv = make_float4(0.f, 0.f, 0.f, 0.f);
        int grow = brow + lr;
        if (grow < NN) xv = *(const float4*)(g_out1 + grow * FHID + kt + lc);
        Xs[lr * 17 + lc + 0] = xv.x;
        Xs[lr * 17 + lc + 1] = xv.y;
        Xs[lr * 17 + lc + 2] = xv.z;
        Xs[lr * 17 + lc + 3] = xv.w;
        __syncthreads();
#pragma unroll
        for (int k = 0; k < 16; k++) {
            float x = Xs[r * 17 + k];
            const float* wp = Ws + (kt + k) * CC + cg * 10;
#pragma unroll
            for (int j = 0; j < 10; j++) acc[j] += x * wp[j];
        }
    }
    int row = brow + r;
    if (row < NN) {
#pragma unroll
        for (int j = 0; j < 10; j++) g_h2[row * CC + cg * 10 + j] = acc[j];
    }
}

// ---------------- attention logits, layer 2 --------------------------------
__global__ void k_alpha2(const float* __restrict__ a2s, const float* __restrict__ a2d) {
    int n = blockIdx.x * blockDim.x + threadIdx.x;
    if (n >= NN) return;
    float s = 0.f, d = 0.f;
#pragma unroll
    for (int k = 0; k < CC; k++) {
        float v = g_h2[n * CC + k];
        s += v * a2s[k];
        d += v * a2d[k];
    }
    g_as2[n] = s;
    g_ad2[n] = d;
}

// ---------------- layer-2 single-pass softmax-agg --------------------------
__global__ void k_agg2(const float* __restrict__ b2, float* __restrict__ out) {
    int v = blockIdx.x;
    int beg = g_rowptr[v], end = g_rowptr[v + 1];
    int deg = end - beg;
    int tid = threadIdx.x;

    __shared__ int   s_src[64];
    __shared__ float s_w[64];
    __shared__ float s_adv;
    if (tid == 0) s_adv = g_ad2[v];

    float acc = 0.f, wsum = 0.f;
    for (int base = 0; base < deg; base += 64) {
        int cnt = min(64, deg - base);
        __syncthreads();                      // covers s_adv (1st iter) + smem reuse
        if (tid < cnt) {
            int s = g_srci[beg + base + tid];
            s_src[tid] = s;
            s_w[tid] = __expf(lrelu(g_as2[s] + s_adv));
        }
        __syncthreads();
        for (int e = 0; e < cnt; e++) {
            float w = s_w[e];
            if (tid < CC) acc += g_h2[s_src[e] * CC + tid] * w;
            wsum += w;
        }
    }
    if (tid < CC) out[v * CC + tid] = acc / (wsum + 1e-16f) + b2[tid];
}

// ---------------- launch ---------------------------------------------------
extern "C" void kernel_launch(void* const* d_in, const int* in_sizes, int n_in,
                              void* d_out, int out_size) {
    const float* x   = (const float*)d_in[0];
    const int*   ei  = (const int*)d_in[1];      // int32 edge_index [2, E]
    const float* W1  = (const float*)d_in[2];
    const float* a1s = (const float*)d_in[3];
    const float* a1d = (const float*)d_in[4];
    const float* b1  = (const float*)d_in[5];
    const float* W2  = (const float*)d_in[6];
    const float* a2s = (const float*)d_in[7];
    const float* a2d = (const float*)d_in[8];
    const float* b2  = (const float*)d_in[9];
    float*       out = (float*)d_out;

    // CSR build (dst-grouped, self-loops first)
    k_init_deg<<<(NN + 255) / 256, 256>>>();
    k_hist<<<(EE + 255) / 256, 256>>>(ei);
    k_scan1<<<SCB, 1024>>>();
    k_scan2<<<1, 32>>>();
    k_scan3<<<SCB, 1024>>>();
    k_selfloop<<<(NN + 255) / 256, 256>>>();
    k_scatter<<<(EE + 255) / 256, 256>>>(ei);

    // fp16 conversions for tensor-core GEMM1
    k_cvtx<<<(NN * FIN / 4 + 255) / 256, 256>>>(x);
    k_cvtw<<<(FHID * FIN + 255) / 256, 256>>>(W1);

    // layer 1
    dim3 g1((NN + 127) / 128, FHID / 32);
    k_gemm1_tc<<<g1, 256>>>();
    k_alpha1<<<NN, 256>>>(a1s, a1d);
    k_agg1<<<NN, 256>>>(b1);

    // layer 2
    k_gemm2<<<(NN + 63) / 64, 256>>>(W2);
    k_alpha2<<<(NN + 255) / 256, 256>>>(a2s, a2d);
    k_agg2<<<NN, 64>>>(b2, out);
}

// round 15
// speedup vs baseline: 1.8984x; 1.0037x over previous
#include <cuda_runtime.h>
#include <cuda_fp16.h>
#include <math.h>

#define NN 50000
#define EE 800000
#define FIN 128
#define HEADS 8
#define HID 32
#define FHID 256          // HEADS*HID
#define CC 40
#define NEG 0.2f
#define AST 136           // padded smem stride (halfs): 272B = 17*16 (uint4-aligned), conflict-free
#define SCB 49            // scan blocks (1024 elems each covers 50176 >= NN)

// ---------------- scratch (static device memory; no allocs allowed) --------
__device__ __half g_h1h[NN * FHID];       // x@W1 (fp16: logits + message gather)
__device__ __half g_xh[NN * FIN];         // x in fp16
__device__ __half g_w1t[FHID * FIN];      // W1 transposed [n][k] fp16
__device__ float  g_out1[NN * FHID];      // elu(agg1 + b1)
__device__ float  g_as1[NN * HEADS];
__device__ float  g_ad1[NN * HEADS];
__device__ float  g_h2[NN * CC];          // out1@W2
__device__ float  g_as2[NN];
__device__ float  g_ad2[NN];
__device__ int    g_cnt[NN];              // degree, then scatter cursor
__device__ int    g_rowptr[NN + 1];
__device__ int    g_bsum[SCB];            // scan partials
__device__ int    g_boff[SCB];            // scan offsets
__device__ int    g_srci[EE + NN];        // src node per CSR slot (self-loops included)

// ---------------- helpers --------------------------------------------------
__device__ __forceinline__ float lrelu(float x) { return x > 0.f ? x : NEG * x; }

// ---------------- CSR build ------------------------------------------------
__global__ void k_init_deg() {
    int v = blockIdx.x * blockDim.x + threadIdx.x;
    if (v < NN) g_cnt[v] = 1;  // self-loop
}

__global__ void k_hist(const int* __restrict__ ei) {
    int e = blockIdx.x * blockDim.x + threadIdx.x;
    if (e < EE) atomicAdd(&g_cnt[ei[EE + e]], 1);
}

// multi-block scan, stage 1: each block inclusive-scans its 1024 elements
__global__ void k_scan1() {
    __shared__ int wsum[32];
    int tid = threadIdx.x, lane = tid & 31, wid = tid >> 5;
    int i = blockIdx.x * 1024 + tid;
    int v = (i < NN) ? g_cnt[i] : 0;
#pragma unroll
    for (int o = 1; o < 32; o <<= 1) {
        int t = __shfl_up_sync(0xffffffffu, v, o);
        if (lane >= o) v += t;
    }
    if (lane == 31) wsum[wid] = v;
    __syncthreads();
    if (wid == 0) {
        int s = wsum[lane];
#pragma unroll
        for (int o = 1; o < 32; o <<= 1) {
            int t = __shfl_up_sync(0xffffffffu, s, o);
            if (lane >= o) s += t;
        }
        wsum[lane] = s;
    }
    __syncthreads();
    int incl = v + (wid ? wsum[wid - 1] : 0);
    if (i < NN) g_rowptr[i + 1] = incl;       // block-local inclusive
    if (tid == 1023) g_bsum[blockIdx.x] = incl;
}

// stage 2: exclusive scan of SCB block sums — simple and covers ALL entries
__global__ void k_scan2() {
    __shared__ int s[SCB];
    int lane = threadIdx.x;
    for (int b = lane; b < SCB; b += 32) s[b] = g_bsum[b];
    __syncwarp();
    if (lane == 0) {
        int acc = 0;
        for (int b = 0; b < SCB; b++) { int t = s[b]; s[b] = acc; acc += t; }
    }
    __syncwarp();
    for (int b = lane; b < SCB; b += 32) g_boff[b] = s[b];
}

// stage 3: add block offsets
__global__ void k_scan3() {
    int i = blockIdx.x * 1024 + threadIdx.x;
    int off = g_boff[blockIdx.x];
    if (i < NN) g_rowptr[i + 1] += off;
    if (i == 0) g_rowptr[0] = 0;
}

__global__ void k_selfloop() {
    int v = blockIdx.x * blockDim.x + threadIdx.x;
    if (v < NN) {
        int p = g_rowptr[v];
        g_srci[p] = v;
        g_cnt[v] = p + 1;   // cursor past self-loop
    }
}

__global__ void k_scatter(const int* __restrict__ ei) {
    int e = blockIdx.x * blockDim.x + threadIdx.x;
    if (e < EE) {
        int dst = ei[EE + e];
        int src = ei[e];
        int pos = atomicAdd(&g_cnt[dst], 1);
        g_srci[pos] = src;
    }
}

// ---------------- fp16 conversions -----------------------------------------
__global__ void k_cvtx(const float* __restrict__ x) {
    int i = blockIdx.x * blockDim.x + threadIdx.x;   // over float4 groups
    if (i < NN * FIN / 4) {
        float4 v = *(const float4*)(x + i * 4);
        __half2 h0 = __floats2half2_rn(v.x, v.y);
        __half2 h1 = __floats2half2_rn(v.z, v.w);
        uint2 u; u.x = *(unsigned*)&h0; u.y = *(unsigned*)&h1;
        *(uint2*)(g_xh + i * 4) = u;
    }
}

__global__ void k_cvtw(const float* __restrict__ W1) {
    int i = blockIdx.x * blockDim.x + threadIdx.x;   // i = n*FIN + k
    if (i < FHID * FIN) {
        int n = i >> 7, k = i & 127;
        g_w1t[i] = __float2half(W1[k * FHID + n]);
    }
}

// ---------------- GEMM1 (tensor core): h1 = x @ W1, fp16 out ---------------
// block tile M128 x N32, K=128 fully resident; 8 warps (4m x 2n), warp m32 x n16
__global__ __launch_bounds__(256) void k_gemm1_tc() {
    __shared__ __half As[128 * AST];
    __shared__ __half Bs[32 * AST];
    int tid = threadIdx.x;
    int warp = tid >> 5, lane = tid & 31;
    int brow = blockIdx.x * 128;
    int bcol = blockIdx.y * 32;

    for (int i = tid; i < 128 * 16; i += 256) {
        int r = i >> 4, c = (i & 15) * 8;
        uint4 v = make_uint4(0, 0, 0, 0);
        int gr = brow + r;
        if (gr < NN) v = *(const uint4*)(g_xh + gr * FIN + c);
        *(uint4*)(As + r * AST + c) = v;
    }
    for (int i = tid; i < 32 * 16; i += 256) {
        int n = i >> 4, c = (i & 15) * 8;
        *(uint4*)(Bs + n * AST + c) = *(const uint4*)(g_w1t + (bcol + n) * FIN + c);
    }
    __syncthreads();

    int wm = (warp & 3) * 32;    // warp m offset
    int wn = (warp >> 2) * 16;   // warp n offset
    int gid = lane >> 2, tig = lane & 3;

    float acc[2][2][4];
#pragma unroll
    for (int mi = 0; mi < 2; mi++)
#pragma unroll
        for (int ni = 0; ni < 2; ni++)
#pragma unroll
            for (int j = 0; j < 4; j++) acc[mi][ni][j] = 0.f;

#pragma unroll
    for (int k0 = 0; k0 < FIN; k0 += 16) {
        unsigned a[2][4], b[2][2];
#pragma unroll
        for (int mi = 0; mi < 2; mi++) {
            const __half* ap = As + (wm + mi * 16 + gid) * AST + k0 + tig * 2;
            a[mi][0] = *(const unsigned*)(ap);
            a[mi][1] = *(const unsigned*)(ap + 8 * AST);
            a[mi][2] = *(const unsigned*)(ap + 8);
            a[mi][3] = *(const unsigned*)(ap + 8 * AST + 8);
        }
#pragma unroll
        for (int ni = 0; ni < 2; ni++) {
            const __half* bp = Bs + (wn + ni * 8 + gid) * AST + k0 + tig * 2;
            b[ni][0] = *(const unsigned*)(bp);
            b[ni][1] = *(const unsigned*)(bp + 8);
        }
#pragma unroll
        for (int mi = 0; mi < 2; mi++)
#pragma unroll
            for (int ni = 0; ni < 2; ni++) {
                asm volatile(
                    "mma.sync.aligned.m16n8k16.row.col.f32.f16.f16.f32 "
                    "{%0,%1,%2,%3}, {%4,%5,%6,%7}, {%8,%9}, {%0,%1,%2,%3};\n"
                    : "+f"(acc[mi][ni][0]), "+f"(acc[mi][ni][1]),
                      "+f"(acc[mi][ni][2]), "+f"(acc[mi][ni][3])
                    : "r"(a[mi][0]), "r"(a[mi][1]), "r"(a[mi][2]), "r"(a[mi][3]),
                      "r"(b[ni][0]), "r"(b[ni][1]));
            }
    }

    // epilogue: fp16 store (half2 per thread, 4B aligned since col is even)
#pragma unroll
    for (int mi = 0; mi < 2; mi++) {
        int r0 = brow + wm + mi * 16 + gid;
#pragma unroll
        for (int ni = 0; ni < 2; ni++) {
            int col = bcol + wn + ni * 8 + tig * 2;
            if (r0 < NN) {
                __half2 h = __floats2half2_rn(acc[mi][ni][0], acc[mi][ni][1]);
                *(__half2*)(g_h1h + r0 * FHID + col) = h;
            }
            if (r0 + 8 < NN) {
                __half2 h = __floats2half2_rn(acc[mi][ni][2], acc[mi][ni][3]);
                *(__half2*)(g_h1h + (r0 + 8) * FHID + col) = h;
            }
        }
    }
}

// ---------------- attention logits, layer 1 (fp16 h1) ----------------------
__global__ void k_alpha1(const float* __restrict__ a1s, const float* __restrict__ a1d) {
    int n = blockIdx.x;
    int tid = threadIdx.x;          // tid = head*32 + d  (matches [8,32] layout)
    int head = tid >> 5, d = tid & 31;
    float v = __half2float(g_h1h[n * FHID + tid]);
    float ps = v * a1s[tid];
    float pd = v * a1d[tid];
#pragma unroll
    for (int o = 16; o; o >>= 1) {
        ps += __shfl_xor_sync(0xffffffffu, ps, o);
        pd += __shfl_xor_sync(0xffffffffu, pd, o);
    }
    if (d == 0) {
        g_as1[n * HEADS + head] = ps;
        g_ad1[n * HEADS + head] = pd;
    }
}

// ---------------- layer-1 single-pass softmax-agg + ELU --------------------
// 256 thr/node (R14 geometry); message gather in fp16 (LDG.16/thread)
__global__ void k_agg1(const float* __restrict__ b1) {
    int v = blockIdx.x;
    int beg = g_rowptr[v], end = g_rowptr[v + 1];
    int deg = end - beg;
    int tid = threadIdx.x, head = tid >> 5;

    __shared__ int   s_src[32];
    __shared__ float s_w[32 * HEADS];
    __shared__ float s_ad[HEADS];
    if (tid < HEADS) s_ad[tid] = g_ad1[v * HEADS + tid];

    float acc = 0.f, wsum = 0.f;
    for (int base = 0; base < deg; base += 32) {
        int cnt = min(32, deg - base);
        __syncthreads();                      // covers s_ad (1st iter) + smem reuse
        int el = tid >> 3, hh = tid & 7;
        if (el < cnt) {
            int s = g_srci[beg + base + el];
            if (hh == 0) s_src[el] = s;
            s_w[el * HEADS + hh] = __expf(lrelu(g_as1[s * HEADS + hh] + s_ad[hh]));
        }
        __syncthreads();
        for (int e = 0; e < cnt; e++) {
            float w = s_w[e * HEADS + head];
            acc += __half2float(g_h1h[s_src[e] * FHID + tid]) * w;
            wsum += w;                        // identical across threads of a head
        }
    }
    float r = acc / (wsum + 1e-16f) + b1[tid];
    g_out1[v * FHID + tid] = r > 0.f ? r : expm1f(r);   // ELU
}

// ---------------- GEMM2: h2 = out1 @ W2  (50000x256 @ 256x40) --------------
__global__ void k_gemm2(const float* __restrict__ W2) {
    __shared__ float Ws[FHID * CC];   // 40 KB
    __shared__ float Xs[64 * 17];
    int tid = threadIdx.x;
    int brow = blockIdx.x * 64;
    for (int i = tid; i < FHID * CC; i += 256) Ws[i] = W2[i];
    int r = tid & 63, cg = tid >> 6;            // 4 col-groups of 10
    int lr = tid >> 2, lc = (tid & 3) * 4;
    float acc[10];
#pragma unroll
    for (int j = 0; j < 10; j++) acc[j] = 0.f;

    for (int kt = 0; kt < FHID; kt += 16) {
        __syncthreads();   // also protects Ws on first iter
        float4 xv = make_float4(0.f, 0.f, 0.f, 0.f);
        int grow = brow + lr;
        if (grow < NN) xv = *(const float4*)(g_out1 + grow * FHID + kt + lc);
        Xs[lr * 17 + lc + 0] = xv.x;
        Xs[lr * 17 + lc + 1] = xv.y;
        Xs[lr * 17 + lc + 2] = xv.z;
        Xs[lr * 17 + lc + 3] = xv.w;
        __syncthreads();
#pragma unroll
        for (int k = 0; k < 16; k++) {
            float x = Xs[r * 17 + k];
            const float* wp = Ws + (kt + k) * CC + cg * 10;
#pragma unroll
            for (int j = 0; j < 10; j++) acc[j] += x * wp[j];
        }
    }
    int row = brow + r;
    if (row < NN) {
#pragma unroll
        for (int j = 0; j < 10; j++) g_h2[row * CC + cg * 10 + j] = acc[j];
    }
}

// ---------------- attention logits, layer 2 --------------------------------
__global__ void k_alpha2(const float* __restrict__ a2s, const float* __restrict__ a2d) {
    int n = blockIdx.x * blockDim.x + threadIdx.x;
    if (n >= NN) return;
    float s = 0.f, d = 0.f;
#pragma unroll
    for (int k = 0; k < CC; k++) {
        float v = g_h2[n * CC + k];
        s += v * a2s[k];
        d += v * a2d[k];
    }
    g_as2[n] = s;
    g_ad2[n] = d;
}

// ---------------- layer-2 single-pass softmax-agg --------------------------
__global__ void k_agg2(const float* __restrict__ b2, float* __restrict__ out) {
    int v = blockIdx.x;
    int beg = g_rowptr[v], end = g_rowptr[v + 1];
    int deg = end - beg;
    int tid = threadIdx.x;

    __shared__ int   s_src[64];
    __shared__ float s_w[64];
    __shared__ float s_adv;
    if (tid == 0) s_adv = g_ad2[v];

    float acc = 0.f, wsum = 0.f;
    for (int base = 0; base < deg; base += 64) {
        int cnt = min(64, deg - base);
        __syncthreads();                      // covers s_adv (1st iter) + smem reuse
        if (tid < cnt) {
            int s = g_srci[beg + base + tid];
            s_src[tid] = s;
            s_w[tid] = __expf(lrelu(g_as2[s] + s_adv));
        }
        __syncthreads();
        for (int e = 0; e < cnt; e++) {
            float w = s_w[e];
            if (tid < CC) acc += g_h2[s_src[e] * CC + tid] * w;
            wsum += w;
        }
    }
    if (tid < CC) out[v * CC + tid] = acc / (wsum + 1e-16f) + b2[tid];
}

// ---------------- launch ---------------------------------------------------
extern "C" void kernel_launch(void* const* d_in, const int* in_sizes, int n_in,
                              void* d_out, int out_size) {
    const float* x   = (const float*)d_in[0];
    const int*   ei  = (const int*)d_in[1];      // int32 edge_index [2, E]
    const float* W1  = (const float*)d_in[2];
    const float* a1s = (const float*)d_in[3];
    const float* a1d = (const float*)d_in[4];
    const float* b1  = (const float*)d_in[5];
    const float* W2  = (const float*)d_in[6];
    const float* a2s = (const float*)d_in[7];
    const float* a2d = (const float*)d_in[8];
    const float* b2  = (const float*)d_in[9];
    float*       out = (float*)d_out;

    // CSR build (dst-grouped, self-loops first)
    k_init_deg<<<(NN + 255) / 256, 256>>>();
    k_hist<<<(EE + 255) / 256, 256>>>(ei);
    k_scan1<<<SCB, 1024>>>();
    k_scan2<<<1, 32>>>();
    k_scan3<<<SCB, 1024>>>();
    k_selfloop<<<(NN + 255) / 256, 256>>>();
    k_scatter<<<(EE + 255) / 256, 256>>>(ei);

    // fp16 conversions for tensor-core GEMM1
    k_cvtx<<<(NN * FIN / 4 + 255) / 256, 256>>>(x);
    k_cvtw<<<(FHID * FIN + 255) / 256, 256>>>(W1);

    // layer 1
    dim3 g1((NN + 127) / 128, FHID / 32);
    k_gemm1_tc<<<g1, 256>>>();
    k_alpha1<<<NN, 256>>>(a1s, a1d);
    k_agg1<<<NN, 256>>>(b1);

    // layer 2
    k_gemm2<<<(NN + 63) / 64, 256>>>(W2);
    k_alpha2<<<(NN + 255) / 256, 256>>>(a2s, a2d);
    k_agg2<<<NN, 64>>>(b2, out);
}

// round 17
// speedup vs baseline: 2.4449x; 1.2879x over previous
#include <cuda_runtime.h>
#include <cuda_fp16.h>
#include <math.h>

#define NN 50000
#define EE 800000
#define FIN 128
#define HEADS 8
#define HID 32
#define FHID 256          // HEADS*HID
#define CC 40
#define NEG 0.2f
#define AST 136           // padded smem stride (halfs): 272B = 17*16 (uint4-aligned), conflict-free
#define SCB 49            // scan blocks (1024 elems each covers 50176 >= NN)

// ---------------- scratch (static device memory; no allocs allowed) --------
__device__ __half g_h1h[NN * FHID];       // x@W1 (fp16: logits + message gather)
__device__ __half g_xh[NN * FIN];         // x in fp16
__device__ __half g_w1t[FHID * FIN];      // W1 transposed [n][k] fp16
__device__ float  g_out1[NN * FHID];      // elu(agg1 + b1)
__device__ float  g_as1[NN * HEADS];
__device__ float  g_ad1[NN * HEADS];
__device__ float  g_h2[NN * CC];          // out1@W2
__device__ float  g_as2[NN];
__device__ float  g_ad2[NN];
__device__ int    g_cnt[NN];              // degree, then scatter cursor
__device__ int    g_rowptr[NN + 1];
__device__ int    g_bsum[SCB];            // scan partials
__device__ int    g_boff[SCB];            // scan offsets
__device__ int    g_srci[EE + NN];        // src node per CSR slot (self-loops included)

// ---------------- helpers --------------------------------------------------
__device__ __forceinline__ float lrelu(float x) { return x > 0.f ? x : NEG * x; }

// ---------------- CSR build ------------------------------------------------
__global__ void k_init_deg() {
    int v = blockIdx.x * blockDim.x + threadIdx.x;
    if (v < NN) g_cnt[v] = 1;  // self-loop
}

__global__ void k_hist(const int* __restrict__ ei) {
    int e = blockIdx.x * blockDim.x + threadIdx.x;
    if (e < EE) atomicAdd(&g_cnt[ei[EE + e]], 1);
}

// multi-block scan, stage 1: each block inclusive-scans its 1024 elements
__global__ void k_scan1() {
    __shared__ int wsum[32];
    int tid = threadIdx.x, lane = tid & 31, wid = tid >> 5;
    int i = blockIdx.x * 1024 + tid;
    int v = (i < NN) ? g_cnt[i] : 0;
#pragma unroll
    for (int o = 1; o < 32; o <<= 1) {
        int t = __shfl_up_sync(0xffffffffu, v, o);
        if (lane >= o) v += t;
    }
    if (lane == 31) wsum[wid] = v;
    __syncthreads();
    if (wid == 0) {
        int s = wsum[lane];
#pragma unroll
        for (int o = 1; o < 32; o <<= 1) {
            int t = __shfl_up_sync(0xffffffffu, s, o);
            if (lane >= o) s += t;
        }
        wsum[lane] = s;
    }
    __syncthreads();
    int incl = v + (wid ? wsum[wid - 1] : 0);
    if (i < NN) g_rowptr[i + 1] = incl;       // block-local inclusive
    if (tid == 1023) g_bsum[blockIdx.x] = incl;
}

// stage 2: exclusive scan of SCB block sums — simple and covers ALL entries
__global__ void k_scan2() {
    __shared__ int s[SCB];
    int lane = threadIdx.x;
    for (int b = lane; b < SCB; b += 32) s[b] = g_bsum[b];
    __syncwarp();
    if (lane == 0) {
        int acc = 0;
        for (int b = 0; b < SCB; b++) { int t = s[b]; s[b] = acc; acc += t; }
    }
    __syncwarp();
    for (int b = lane; b < SCB; b += 32) g_boff[b] = s[b];
}

// stage 3: add block offsets
__global__ void k_scan3() {
    int i = blockIdx.x * 1024 + threadIdx.x;
    int off = g_boff[blockIdx.x];
    if (i < NN) g_rowptr[i + 1] += off;
    if (i == 0) g_rowptr[0] = 0;
}

__global__ void k_selfloop() {
    int v = blockIdx.x * blockDim.x + threadIdx.x;
    if (v < NN) {
        int p = g_rowptr[v];
        g_srci[p] = v;
        g_cnt[v] = p + 1;   // cursor past self-loop
    }
}

__global__ void k_scatter(const int* __restrict__ ei) {
    int e = blockIdx.x * blockDim.x + threadIdx.x;
    if (e < EE) {
        int dst = ei[EE + e];
        int src = ei[e];
        int pos = atomicAdd(&g_cnt[dst], 1);
        g_srci[pos] = src;
    }
}

// ---------------- fp16 conversions -----------------------------------------
__global__ void k_cvtx(const float* __restrict__ x) {
    int i = blockIdx.x * blockDim.x + threadIdx.x;   // over float4 groups
    if (i < NN * FIN / 4) {
        float4 v = *(const float4*)(x + i * 4);
        __half2 h0 = __floats2half2_rn(v.x, v.y);
        __half2 h1 = __floats2half2_rn(v.z, v.w);
        uint2 u; u.x = *(unsigned*)&h0; u.y = *(unsigned*)&h1;
        *(uint2*)(g_xh + i * 4) = u;
    }
}

__global__ void k_cvtw(const float* __restrict__ W1) {
    int i = blockIdx.x * blockDim.x + threadIdx.x;   // i = n*FIN + k
    if (i < FHID * FIN) {
        int n = i >> 7, k = i & 127;
        g_w1t[i] = __float2half(W1[k * FHID + n]);
    }
}

// ---------------- GEMM1 (tensor core): h1 = x @ W1, fp16 out ---------------
// block tile M128 x N32, K=128 fully resident; 8 warps (4m x 2n), warp m32 x n16
__global__ __launch_bounds__(256) void k_gemm1_tc() {
    __shared__ __half As[128 * AST];
    __shared__ __half Bs[32 * AST];
    int tid = threadIdx.x;
    int warp = tid >> 5, lane = tid & 31;
    int brow = blockIdx.x * 128;
    int bcol = blockIdx.y * 32;

    for (int i = tid; i < 128 * 16; i += 256) {
        int r = i >> 4, c = (i & 15) * 8;
        uint4 v = make_uint4(0, 0, 0, 0);
        int gr = brow + r;
        if (gr < NN) v = *(const uint4*)(g_xh + gr * FIN + c);
        *(uint4*)(As + r * AST + c) = v;
    }
    for (int i = tid; i < 32 * 16; i += 256) {
        int n = i >> 4, c = (i & 15) * 8;
        *(uint4*)(Bs + n * AST + c) = *(const uint4*)(g_w1t + (bcol + n) * FIN + c);
    }
    __syncthreads();

    int wm = (warp & 3) * 32;    // warp m offset
    int wn = (warp >> 2) * 16;   // warp n offset
    int gid = lane >> 2, tig = lane & 3;

    float acc[2][2][4];
#pragma unroll
    for (int mi = 0; mi < 2; mi++)
#pragma unroll
        for (int ni = 0; ni < 2; ni++)
#pragma unroll
            for (int j = 0; j < 4; j++) acc[mi][ni][j] = 0.f;

#pragma unroll
    for (int k0 = 0; k0 < FIN; k0 += 16) {
        unsigned a[2][4], b[2][2];
#pragma unroll
        for (int mi = 0; mi < 2; mi++) {
            const __half* ap = As + (wm + mi * 16 + gid) * AST + k0 + tig * 2;
            a[mi][0] = *(const unsigned*)(ap);
            a[mi][1] = *(const unsigned*)(ap + 8 * AST);
            a[mi][2] = *(const unsigned*)(ap + 8);
            a[mi][3] = *(const unsigned*)(ap + 8 * AST + 8);
        }
#pragma unroll
        for (int ni = 0; ni < 2; ni++) {
            const __half* bp = Bs + (wn + ni * 8 + gid) * AST + k0 + tig * 2;
            b[ni][0] = *(const unsigned*)(bp);
            b[ni][1] = *(const unsigned*)(bp + 8);
        }
#pragma unroll
        for (int mi = 0; mi < 2; mi++)
#pragma unroll
            for (int ni = 0; ni < 2; ni++) {
                asm volatile(
                    "mma.sync.aligned.m16n8k16.row.col.f32.f16.f16.f32 "
                    "{%0,%1,%2,%3}, {%4,%5,%6,%7}, {%8,%9}, {%0,%1,%2,%3};\n"
                    : "+f"(acc[mi][ni][0]), "+f"(acc[mi][ni][1]),
                      "+f"(acc[mi][ni][2]), "+f"(acc[mi][ni][3])
                    : "r"(a[mi][0]), "r"(a[mi][1]), "r"(a[mi][2]), "r"(a[mi][3]),
                      "r"(b[ni][0]), "r"(b[ni][1]));
            }
    }

    // epilogue: fp16 store (half2 per thread, 4B aligned since col is even)
#pragma unroll
    for (int mi = 0; mi < 2; mi++) {
        int r0 = brow + wm + mi * 16 + gid;
#pragma unroll
        for (int ni = 0; ni < 2; ni++) {
            int col = bcol + wn + ni * 8 + tig * 2;
            if (r0 < NN) {
                __half2 h = __floats2half2_rn(acc[mi][ni][0], acc[mi][ni][1]);
                *(__half2*)(g_h1h + r0 * FHID + col) = h;
            }
            if (r0 + 8 < NN) {
                __half2 h = __floats2half2_rn(acc[mi][ni][2], acc[mi][ni][3]);
                *(__half2*)(g_h1h + (r0 + 8) * FHID + col) = h;
            }
        }
    }
}

// ---------------- attention logits, layer 1 (fp16 h1) ----------------------
__global__ void k_alpha1(const float* __restrict__ a1s, const float* __restrict__ a1d) {
    int n = blockIdx.x;
    int tid = threadIdx.x;          // tid = head*32 + d  (matches [8,32] layout)
    int head = tid >> 5, d = tid & 31;
    float v = __half2float(g_h1h[n * FHID + tid]);
    float ps = v * a1s[tid];
    float pd = v * a1d[tid];
#pragma unroll
    for (int o = 16; o; o >>= 1) {
        ps += __shfl_xor_sync(0xffffffffu, ps, o);
        pd += __shfl_xor_sync(0xffffffffu, pd, o);
    }
    if (d == 0) {
        g_as1[n * HEADS + head] = ps;
        g_ad1[n * HEADS + head] = pd;
    }
}

// ---------------- layer-1 single-pass softmax-agg + ELU: warp per node -----
// lane owns 8 contiguous fp16 features (16B uint4) -> 1 LDG.128 per edge per warp.
// head = lane>>2 (features lane*8..lane*8+7 all in head lane>>2).
__global__ __launch_bounds__(256) void k_agg1w(const float* __restrict__ b1) {
    int w = (blockIdx.x * blockDim.x + threadIdx.x) >> 5;
    if (w >= NN) return;
    int lane = threadIdx.x & 31;
    int head = lane >> 2;
    int beg = g_rowptr[w], deg = g_rowptr[w + 1] - beg;
    float adv = g_ad1[w * HEADS + head];

    const uint4* hp = (const uint4*)g_h1h;   // 32 uint4 per node row
    float acc[8] = {0.f, 0.f, 0.f, 0.f, 0.f, 0.f, 0.f, 0.f};
    float wsum = 0.f;

    for (int base = 0; base < deg; base += 32) {
        int cnt = min(32, deg - base);
        int s_pre = (lane < cnt) ? g_srci[beg + base + lane] : 0;  // coalesced, 1 LDG/32 edges
#pragma unroll 4
        for (int e = 0; e < cnt; e++) {
            int s = __shfl_sync(0xffffffffu, s_pre, e);
            float wt = __expf(lrelu(g_as1[s * HEADS + head] + adv));
            uint4 u = hp[s * (FHID / 8) + lane];
            float2 f0 = __half22float2(*(__half2*)&u.x);
            float2 f1 = __half22float2(*(__half2*)&u.y);
            float2 f2 = __half22float2(*(__half2*)&u.z);
            float2 f3 = __half22float2(*(__half2*)&u.w);
            acc[0] += wt * f0.x; acc[1] += wt * f0.y;
            acc[2] += wt * f1.x; acc[3] += wt * f1.y;
            acc[4] += wt * f2.x; acc[5] += wt * f2.y;
            acc[6] += wt * f3.x; acc[7] += wt * f3.y;
            wsum += wt;
        }
    }
    float inv = 1.f / (wsum + 1e-16f);
    float4 bv0 = *(const float4*)(b1 + lane * 8);
    float4 bv1 = *(const float4*)(b1 + lane * 8 + 4);
    float r0 = acc[0] * inv + bv0.x, r1 = acc[1] * inv + bv0.y;
    float r2 = acc[2] * inv + bv0.z, r3 = acc[3] * inv + bv0.w;
    float r4 = acc[4] * inv + bv1.x, r5 = acc[5] * inv + bv1.y;
    float r6 = acc[6] * inv + bv1.z, r7 = acc[7] * inv + bv1.w;
    float* op = g_out1 + w * FHID + lane * 8;
    *(float4*)op = make_float4(r0 > 0.f ? r0 : expm1f(r0), r1 > 0.f ? r1 : expm1f(r1),
                               r2 > 0.f ? r2 : expm1f(r2), r3 > 0.f ? r3 : expm1f(r3));
    *(float4*)(op + 4) = make_float4(r4 > 0.f ? r4 : expm1f(r4), r5 > 0.f ? r5 : expm1f(r5),
                                     r6 > 0.f ? r6 : expm1f(r6), r7 > 0.f ? r7 : expm1f(r7));
}

// ---------------- GEMM2: h2 = out1 @ W2  (50000x256 @ 256x40) --------------
__global__ void k_gemm2(const float* __restrict__ W2) {
    __shared__ float Ws[FHID * CC];   // 40 KB
    __shared__ float Xs[64 * 17];
    int tid = threadIdx.x;
    int brow = blockIdx.x * 64;
    for (int i = tid; i < FHID * CC; i += 256) Ws[i] = W2[i];
    int r = tid & 63, cg = tid >> 6;            // 4 col-groups of 10
    int lr = tid >> 2, lc = (tid & 3) * 4;
    float acc[10];
#pragma unroll
    for (int j = 0; j < 10; j++) acc[j] = 0.f;

    for (int kt = 0; kt < FHID; kt += 16) {
        __syncthreads();   // also protects Ws on first iter
        float4 xv = make_float4(0.f, 0.f, 0.f, 0.f);
        int grow = brow + lr;
        if (grow < NN) xv = *(const float4*)(g_out1 + grow * FHID + kt + lc);
        Xs[lr * 17 + lc + 0] = xv.x;
        Xs[lr * 17 + lc + 1] = xv.y;
        Xs[lr * 17 + lc + 2] = xv.z;
        Xs[lr * 17 + lc + 3] = xv.w;
        __syncthreads();
#pragma unroll
        for (int k = 0; k < 16; k++) {
            float x = Xs[r * 17 + k];
            const float* wp = Ws + (kt + k) * CC + cg * 10;
#pragma unroll
            for (int j = 0; j < 10; j++) acc[j] += x * wp[j];
        }
    }
    int row = brow + r;
    if (row < NN) {
#pragma unroll
        for (int j = 0; j < 10; j++) g_h2[row * CC + cg * 10 + j] = acc[j];
    }
}

// ---------------- attention logits, layer 2 --------------------------------
__global__ void k_alpha2(const float* __restrict__ a2s, const float* __restrict__ a2d) {
    int n = blockIdx.x * blockDim.x + threadIdx.x;
    if (n >= NN) return;
    float s = 0.f, d = 0.f;
#pragma unroll
    for (int k = 0; k < CC; k++) {
        float v = g_h2[n * CC + k];
        s += v * a2s[k];
        d += v * a2d[k];
    }
    g_as2[n] = s;
    g_ad2[n] = d;
}

// ---------------- layer-2 single-pass softmax-agg --------------------------
__global__ void k_agg2(const float* __restrict__ b2, float* __restrict__ out) {
    int v = blockIdx.x;
    int beg = g_rowptr[v], end = g_rowptr[v + 1];
    int deg = end - beg;
    int tid = threadIdx.x;

    __shared__ int   s_src[64];
    __shared__ float s_w[64];
    __shared__ float s_adv;
    if (tid == 0) s_adv = g_ad2[v];

    float acc = 0.f, wsum = 0.f;
    for (int base = 0; base < deg; base += 64) {
        int cnt = min(64, deg - base);
        __syncthreads();                      // covers s_adv (1st iter) + smem reuse
        if (tid < cnt) {
            int s = g_srci[beg + base + tid];
            s_src[tid] = s;
            s_w[tid] = __expf(lrelu(g_as2[s] + s_adv));
        }
        __syncthreads();
        for (int e = 0; e < cnt; e++) {
            float w = s_w[e];
            if (tid < CC) acc += g_h2[s_src[e] * CC + tid] * w;
            wsum += w;
        }
    }
    if (tid < CC) out[v * CC + tid] = acc / (wsum + 1e-16f) + b2[tid];
}

// ---------------- launch ---------------------------------------------------
extern "C" void kernel_launch(void* const* d_in, const int* in_sizes, int n_in,
                              void* d_out, int out_size) {
    const float* x   = (const float*)d_in[0];
    const int*   ei  = (const int*)d_in[1];      // int32 edge_index [2, E]
    const float* W1  = (const float*)d_in[2];
    const float* a1s = (const float*)d_in[3];
    const float* a1d = (const float*)d_in[4];
    const float* b1  = (const float*)d_in[5];
    const float* W2  = (const float*)d_in[6];
    const float* a2s = (const float*)d_in[7];
    const float* a2d = (const float*)d_in[8];
    const float* b2  = (const float*)d_in[9];
    float*       out = (float*)d_out;

    // CSR build (dst-grouped, self-loops first)
    k_init_deg<<<(NN + 255) / 256, 256>>>();
    k_hist<<<(EE + 255) / 256, 256>>>(ei);
    k_scan1<<<SCB, 1024>>>();
    k_scan2<<<1, 32>>>();
    k_scan3<<<SCB, 1024>>>();
    k_selfloop<<<(NN + 255) / 256, 256>>>();
    k_scatter<<<(EE + 255) / 256, 256>>>(ei);

    // fp16 conversions for tensor-core GEMM1
    k_cvtx<<<(NN * FIN / 4 + 255) / 256, 256>>>(x);
    k_cvtw<<<(FHID * FIN + 255) / 256, 256>>>(W1);

    // layer 1
    dim3 g1((NN + 127) / 128, FHID / 32);
    k_gemm1_tc<<<g1, 256>>>();
    k_alpha1<<<NN, 256>>>(a1s, a1d);
    k_agg1w<<<(NN * 32 + 255) / 256, 256>>>(b1);

    // layer 2
    k_gemm2<<<(NN + 63) / 64, 256>>>(W2);
    k_alpha2<<<(NN + 255) / 256, 256>>>(a2s, a2d);
    k_agg2<<<NN, 64>>>(b2, out);
}